// round 2
// baseline (speedup 1.0000x reference)
#include <cuda_runtime.h>
#include <math.h>

#define Dd 64
#define Nn 8192
#define Mm 256
#define NH 32
#define DN     0.3535533905932738f   /* 64^-0.25 */
#define RATIO  0.0625f               /* 256^-0.5 */
#define REPS   6.25e-8f              /* RATIO * 1e-6 */
#define DIAGC  0.0625f               /* DN^2 * 0.5 */

// ---------------- scratch (device globals; no allocation) ----------------
__device__ float    g_projT[64 * 256];                    // [d][m], pre-scaled by DN
__device__ float    g_kbuf[(size_t)NH * Nn * Mm];         // [head][n][m] : u - diag
__device__ unsigned g_kmax[NH];                           // per-head max(raw u) as ordered key
__device__ float    g_kvpart[(size_t)NH * 16 * 256 * 68]; // [head][slice][m][68]
__device__ float    g_kvaug[(size_t)NH * 256 * 68];       // [head][m][0..63]=kv, [64]=knorm

// order-preserving float<->uint key
static __device__ __forceinline__ unsigned fkey(float f) {
    unsigned b = __float_as_uint(f);
    return (b & 0x80000000u) ? ~b : (b | 0x80000000u);
}

// branch-free exp in FMA/ALU pipes (no MUFU). Valid for x <= 0 (our case), ~2.4e-6 rel err.
static __device__ __forceinline__ float fexp(float x) {
    float t = x * 1.4426950408889634f;
    t = fmaxf(t, -125.0f);
    float r  = t + 12582912.0f;            // round-to-nearest via magic number
    float fi = r - 12582912.0f;
    float f  = t - fi;                      // f in [-0.5, 0.5]
    float p = 1.3333558e-3f;
    p = fmaf(p, f, 9.6181291e-3f);
    p = fmaf(p, f, 5.5504109e-2f);
    p = fmaf(p, f, 2.4022651e-1f);
    p = fmaf(p, f, 6.9314718e-1f);
    p = fmaf(p, f, 1.0f);
    int ib = __float_as_int(r) - 0x4B400000; // integer part
    float s = __int_as_float((ib + 127) << 23);
    return p * s;
}

// ---------------- K0: scaled projT + reset kmax ----------------
__global__ void k_init(const float* __restrict__ proj)
{
    int idx = blockIdx.x * 256 + threadIdx.x;
    if (idx < 64 * 256) {
        int d = idx >> 8, m = idx & 255;
        g_projT[idx] = proj[m * 64 + d] * DN;
    }
    if (idx < NH) g_kmax[idx] = 0u;
}

// ---------------- K1: key projection -> g_kbuf (u - diag), + head max --------
// Grid (128, 32). Block 256. Tile 256(m) x 64(n), K=64. 8x8 register tile/thread.
__global__ void __launch_bounds__(256) k_proj_keys(const float* __restrict__ key)
{
    extern __shared__ float sm[];
    float* Ps = sm;            // [64][256]
    float* Xs = sm + 16384;    // [64][64]
    __shared__ float red[8];

    const int t = threadIdx.x;
    const int head = blockIdx.y;
    const int n0 = blockIdx.x * 64;

    {   // stage projT (already [d][m] scaled)
        const float4* s4 = (const float4*)g_projT;
        float4* d4 = (float4*)Ps;
        #pragma unroll
        for (int r = 0; r < 16; r++) d4[t + 256 * r] = s4[t + 256 * r];
    }
    {   // stage key tile [64d][64n]
        const float* kp = key + (size_t)head * Dd * Nn;
        #pragma unroll
        for (int r = 0; r < 4; r++) {
            int e4 = t + 256 * r;
            int dd = e4 >> 4, n4 = e4 & 15;
            *(float4*)(Xs + dd * 64 + n4 * 4) =
                *(const float4*)(kp + (size_t)dd * Nn + n0 + n4 * 4);
        }
    }
    __syncthreads();

    const int tm  = (t >> 3) << 3;   // m base
    const int tn4 = (t & 7) << 2;    // n base within half

    float acc[8][8];
    float qsq[8];
    #pragma unroll
    for (int i = 0; i < 8; i++) {
        qsq[i] = 0.0f;
        #pragma unroll
        for (int j = 0; j < 8; j++) acc[i][j] = 0.0f;
    }

    #pragma unroll 8
    for (int kk = 0; kk < 64; kk++) {
        float4 a0 = *(const float4*)(Ps + kk * 256 + tm);
        float4 a1 = *(const float4*)(Ps + kk * 256 + tm + 4);
        float4 b0 = *(const float4*)(Xs + kk * 64 + tn4);
        float4 b1 = *(const float4*)(Xs + kk * 64 + 32 + tn4);
        float av[8] = {a0.x,a0.y,a0.z,a0.w,a1.x,a1.y,a1.z,a1.w};
        float bv[8] = {b0.x,b0.y,b0.z,b0.w,b1.x,b1.y,b1.z,b1.w};
        #pragma unroll
        for (int j = 0; j < 8; j++) {
            qsq[j] = fmaf(bv[j], bv[j], qsq[j]);
            #pragma unroll
            for (int i = 0; i < 8; i++) acc[i][j] = fmaf(av[i], bv[j], acc[i][j]);
        }
    }

    // block max of raw u -> atomicMax per head
    float bm = -3.4e38f;
    #pragma unroll
    for (int i = 0; i < 8; i++)
        #pragma unroll
        for (int j = 0; j < 8; j++) bm = fmaxf(bm, acc[i][j]);
    #pragma unroll
    for (int o = 16; o; o >>= 1) bm = fmaxf(bm, __shfl_xor_sync(0xffffffffu, bm, o));
    if ((t & 31) == 0) red[t >> 5] = bm;
    __syncthreads();
    if (t == 0) {
        float m0 = red[0];
        #pragma unroll
        for (int w = 1; w < 8; w++) m0 = fmaxf(m0, red[w]);
        atomicMax(g_kmax + head, fkey(m0));
    }

    // write u - diag, layout [head][n][m]
    float* gb = g_kbuf + ((size_t)head * Nn + n0) * Mm;
    #pragma unroll
    for (int j = 0; j < 8; j++) {
        int n = (j < 4) ? (tn4 + j) : (28 + tn4 + j);
        float dg = qsq[j] * DIAGC;
        *(float4*)(gb + (size_t)n * Mm + tm) =
            make_float4(acc[0][j]-dg, acc[1][j]-dg, acc[2][j]-dg, acc[3][j]-dg);
        *(float4*)(gb + (size_t)n * Mm + tm + 4) =
            make_float4(acc[4][j]-dg, acc[5][j]-dg, acc[6][j]-dg, acc[7][j]-dg);
    }
}

// ---------------- K2: k_phi + partial kv/knorm ----------------
// Grid (16 slices, 32 heads). Block 256. Each block: 512 tokens, 16 chunks of 32.
__global__ void __launch_bounds__(256) k_kv_accum(const float* __restrict__ value)
{
    __shared__ float PHIs[32 * 264];   // [n][m] padded
    __shared__ float Vs[32 * 68];      // [n][d] padded

    const int t = threadIdx.x;
    const int head = blockIdx.y;
    const int slice = blockIdx.x;
    const float kmax = [](unsigned k){
        return __uint_as_float((k & 0x80000000u) ? (k & 0x7fffffffu) : ~k);
    }(g_kmax[head]);

    const int tm = (t >> 3) << 3;   // m base (0..248)
    const int td = (t & 7) << 3;    // d base (0..56)

    float acc[8][8];
    float nrm[8];
    #pragma unroll
    for (int i = 0; i < 8; i++) {
        nrm[i] = 0.0f;
        #pragma unroll
        for (int j = 0; j < 8; j++) acc[i][j] = 0.0f;
    }

    const float* vp = value + (size_t)head * Dd * Nn;
    const float* kb = g_kbuf + ((size_t)head * Nn + (size_t)slice * 512) * Mm;

    for (int c = 0; c < 16; c++) {
        const int n0 = slice * 512 + c * 32;
        __syncthreads();
        {   // stage PHI[n][m] with exp applied
            const float4* src = (const float4*)(kb + (size_t)c * 32 * Mm);
            #pragma unroll
            for (int r = 0; r < 8; r++) {
                int e4 = t + 256 * r;
                int n = e4 >> 6, m4 = e4 & 63;
                float4 v = src[(size_t)n * 64 + m4];
                float4 p;
                p.x = RATIO * fexp(v.x - kmax) + REPS;
                p.y = RATIO * fexp(v.y - kmax) + REPS;
                p.z = RATIO * fexp(v.z - kmax) + REPS;
                p.w = RATIO * fexp(v.w - kmax) + REPS;
                *(float4*)(PHIs + n * 264 + m4 * 4) = p;
            }
        }
        {   // stage Vs[n][d]
            #pragma unroll
            for (int r = 0; r < 8; r++) {
                int idx = t + 256 * r;
                int n = idx & 31, d = idx >> 5;
                Vs[n * 68 + d] = vp[(size_t)d * Nn + n0 + n];
            }
        }
        __syncthreads();

        #pragma unroll 4
        for (int n = 0; n < 32; n++) {
            float4 a0 = *(const float4*)(PHIs + n * 264 + tm);
            float4 a1 = *(const float4*)(PHIs + n * 264 + tm + 4);
            float4 b0 = *(const float4*)(Vs + n * 68 + td);
            float4 b1 = *(const float4*)(Vs + n * 68 + td + 4);
            float av[8] = {a0.x,a0.y,a0.z,a0.w,a1.x,a1.y,a1.z,a1.w};
            float bv[8] = {b0.x,b0.y,b0.z,b0.w,b1.x,b1.y,b1.z,b1.w};
            if ((t & 7) == 0) {
                #pragma unroll
                for (int i = 0; i < 8; i++) nrm[i] += av[i];
            }
            #pragma unroll
            for (int j = 0; j < 8; j++)
                #pragma unroll
                for (int i = 0; i < 8; i++) acc[i][j] = fmaf(av[i], bv[j], acc[i][j]);
        }
    }

    float* dst = g_kvpart + (size_t)(head * 16 + slice) * 17408;
    #pragma unroll
    for (int i = 0; i < 8; i++) {
        *(float4*)(dst + (tm + i) * 68 + td) =
            make_float4(acc[i][0], acc[i][1], acc[i][2], acc[i][3]);
        *(float4*)(dst + (tm + i) * 68 + td + 4) =
            make_float4(acc[i][4], acc[i][5], acc[i][6], acc[i][7]);
        if ((t & 7) == 0) dst[(tm + i) * 68 + 64] = nrm[i];
    }
}

// ---------------- K3: reduce partials -> g_kvaug ----------------
__global__ void k_reduce()
{
    int idx = blockIdx.x * 256 + threadIdx.x;   // < 32*17408
    int h = idx / 17408;
    int j = idx - h * 17408;
    float s = 0.0f;
    if (j % 68 < 65) {
        #pragma unroll
        for (int sl = 0; sl < 16; sl++)
            s += g_kvpart[(size_t)(h * 16 + sl) * 17408 + j];
    }
    g_kvaug[idx] = s;
}

// ---------------- K4: query projection + phi + output ----------------
// Grid (128, 32). Block 256.
__global__ void __launch_bounds__(256) k_query_out(const float* __restrict__ query,
                                                   float* __restrict__ out)
{
    extern __shared__ float sm[];
    float* Ps   = sm;            // phase A: [64][256]
    float* Xs   = sm + 16384;    // phase A: [64][64]
    float* PHIs = sm;            // phase B: [256][68]  (m rows, n cols)
    float* KVs  = sm + 17408;    // phase B: [256][68]
    __shared__ float redm[32 * 64];
    __shared__ float stab[64];

    const int t = threadIdx.x;
    const int head = blockIdx.y;
    const int n0 = blockIdx.x * 64;

    {
        const float4* s4 = (const float4*)g_projT;
        float4* d4 = (float4*)Ps;
        #pragma unroll
        for (int r = 0; r < 16; r++) d4[t + 256 * r] = s4[t + 256 * r];
    }
    {
        const float* qp = query + (size_t)head * Dd * Nn;
        #pragma unroll
        for (int r = 0; r < 4; r++) {
            int e4 = t + 256 * r;
            int dd = e4 >> 4, n4 = e4 & 15;
            *(float4*)(Xs + dd * 64 + n4 * 4) =
                *(const float4*)(qp + (size_t)dd * Nn + n0 + n4 * 4);
        }
    }
    __syncthreads();

    const int tm  = (t >> 3) << 3;
    const int tn4 = (t & 7) << 2;

    float acc[8][8];
    float qsq[8];
    #pragma unroll
    for (int i = 0; i < 8; i++) {
        qsq[i] = 0.0f;
        #pragma unroll
        for (int j = 0; j < 8; j++) acc[i][j] = 0.0f;
    }

    #pragma unroll 8
    for (int kk = 0; kk < 64; kk++) {
        float4 a0 = *(const float4*)(Ps + kk * 256 + tm);
        float4 a1 = *(const float4*)(Ps + kk * 256 + tm + 4);
        float4 b0 = *(const float4*)(Xs + kk * 64 + tn4);
        float4 b1 = *(const float4*)(Xs + kk * 64 + 32 + tn4);
        float av[8] = {a0.x,a0.y,a0.z,a0.w,a1.x,a1.y,a1.z,a1.w};
        float bv[8] = {b0.x,b0.y,b0.z,b0.w,b1.x,b1.y,b1.z,b1.w};
        #pragma unroll
        for (int j = 0; j < 8; j++) {
            qsq[j] = fmaf(bv[j], bv[j], qsq[j]);
            #pragma unroll
            for (int i = 0; i < 8; i++) acc[i][j] = fmaf(av[i], bv[j], acc[i][j]);
        }
    }

    // per-column (token) max of raw u
    #pragma unroll
    for (int j = 0; j < 8; j++) {
        int col = (j < 4) ? (tn4 + j) : (28 + tn4 + j);
        float lm = acc[0][j];
        #pragma unroll
        for (int i = 1; i < 8; i++) lm = fmaxf(lm, acc[i][j]);
        redm[(t >> 3) * 64 + col] = lm;
    }
    __syncthreads();   // barrier A: phase-A smem reads complete, redm written

    {   // stage KVs (linear copy, [256][68] padded layout matches global)
        const float4* s4 = (const float4*)(g_kvaug + (size_t)head * 17408);
        float4* d4 = (float4*)KVs;
        #pragma unroll
        for (int r = 0; r < 17; r++) d4[t + 256 * r] = s4[t + 256 * r];
    }
    if (t < 64) {
        float m0 = redm[t];
        #pragma unroll
        for (int r2 = 1; r2 < 32; r2++) m0 = fmaxf(m0, redm[r2 * 64 + t]);
        stab[t] = m0;
    }
    __syncthreads();   // barrier B: stab ready, KVs ready

    // write PHIs[m][n]
    #pragma unroll
    for (int j = 0; j < 8; j++) {
        int col = (j < 4) ? (tn4 + j) : (28 + tn4 + j);
        float cc = -qsq[j] * DIAGC - stab[col];
        #pragma unroll
        for (int i = 0; i < 8; i++)
            PHIs[(tm + i) * 68 + col] = RATIO * fexp(acc[i][j] + cc) + REPS;
    }
    __syncthreads();   // barrier C

    // phase B: out[n][d] = sum_m phi[m][n] * kv[m][d];  norm via kv[m][64]
    const int qn = (t & 15) << 2;   // n offset 0..60
    const int qd = (t >> 4) << 2;   // d offset 0..60
    float oa[4][4];
    float on[4];
    #pragma unroll
    for (int j = 0; j < 4; j++) {
        on[j] = 0.0f;
        #pragma unroll
        for (int d2 = 0; d2 < 4; d2++) oa[j][d2] = 0.0f;
    }

    #pragma unroll 4
    for (int m = 0; m < 256; m++) {
        float4 p  = *(const float4*)(PHIs + m * 68 + qn);
        float4 kv = *(const float4*)(KVs + m * 68 + qd);
        float  kn = KVs[m * 68 + 64];
        float pv[4]  = {p.x, p.y, p.z, p.w};
        float kvv[4] = {kv.x, kv.y, kv.z, kv.w};
        #pragma unroll
        for (int j = 0; j < 4; j++) {
            on[j] = fmaf(pv[j], kn, on[j]);
            #pragma unroll
            for (int d2 = 0; d2 < 4; d2++)
                oa[j][d2] = fmaf(pv[j], kvv[d2], oa[j][d2]);
        }
    }

    float rn[4];
    #pragma unroll
    for (int j = 0; j < 4; j++) rn[j] = 1.0f / on[j];

    float* op = out + (size_t)head * Dd * Nn + n0 + qn;
    #pragma unroll
    for (int d2 = 0; d2 < 4; d2++) {
        *(float4*)(op + (size_t)(qd + d2) * Nn) =
            make_float4(oa[0][d2] * rn[0], oa[1][d2] * rn[1],
                        oa[2][d2] * rn[2], oa[3][d2] * rn[3]);
    }
}

// ---------------- launch ----------------
extern "C" void kernel_launch(void* const* d_in, const int* in_sizes, int n_in,
                              void* d_out, int out_size)
{
    const float* query = (const float*)d_in[0];
    const float* key   = (const float*)d_in[1];
    const float* value = (const float*)d_in[2];
    const float* proj  = (const float*)d_in[3];
    float* out = (float*)d_out;

    cudaFuncSetAttribute(k_proj_keys, cudaFuncAttributeMaxDynamicSharedMemorySize, 81920);
    cudaFuncSetAttribute(k_query_out, cudaFuncAttributeMaxDynamicSharedMemorySize, 139264);

    k_init<<<64, 256>>>(proj);
    k_proj_keys<<<dim3(128, 32), 256, 81920>>>(key);
    k_kv_accum<<<dim3(16, 32), 256>>>(value);
    k_reduce<<<2176, 256>>>();
    k_query_out<<<dim3(128, 32), 256, 139264>>>(query, out);
}